// round 1
// baseline (speedup 1.0000x reference)
#include <cuda_runtime.h>
#include <cstdint>

// Problem constants
#define B_    8
#define T_    16
#define HW_   196
#define TS_   3136      // T_*HW_
#define CA_   384
#define CIN_  768
#define L_    197
#define BT_   128
#define M_    25088     // BT_*196

// Scratch (device globals — no allocations allowed)
__device__ float g_h1t[M_ * CA_];   // fc1 out, token-major [m][a]
__device__ float g_h1 [M_ * CA_];   // [b][a][t*196+sp]
__device__ float g_h2 [M_ * CA_];   // conv out, [b][a][ts]
__device__ float g_h2t[M_ * CA_];   // token-major [m][a]

__device__ __forceinline__ float to_tf32(float f) {
    uint32_t u;
    asm("cvt.rna.tf32.f32 %0, %1;" : "=r"(u) : "f"(f));
    return __uint_as_float(u);
}

__device__ __forceinline__ void mma_tf32(float* d, const uint32_t* a, const uint32_t* b) {
    asm volatile(
        "mma.sync.aligned.m16n8k8.row.col.f32.tf32.tf32.f32 "
        "{%0,%1,%2,%3}, {%4,%5,%6,%7}, {%8,%9}, {%0,%1,%2,%3};\n"
        : "+f"(d[0]), "+f"(d[1]), "+f"(d[2]), "+f"(d[3])
        : "r"(a[0]), "r"(a[1]), "r"(a[2]), "r"(a[3]), "r"(b[0]), "r"(b[1]));
}

#define BM 128
#define BN 64
#define BK 16
#define LDA 20   // padded smem row stride (floats): 20*g+tig mod 32 covers all banks

// out = A[M,K] @ W[N,K]^T + bias   (W row-major [N][K] == B col-major)
// FC2=false: A = x tokens (skip CLS), out = g_h1t
// FC2=true : A = g_h2t, out = d_out with residual x add
template<bool FC2>
__global__ __launch_bounds__(256) void gemm_k(
    const float* __restrict__ Ap, const float* __restrict__ W,
    const float* __restrict__ bias, const float* __restrict__ xres,
    float* __restrict__ outp)
{
    constexpr int K = FC2 ? CA_ : CIN_;
    __shared__ float As[2][BM * LDA];
    __shared__ float Bs[2][BN * LDA];

    const float* A = FC2 ? (const float*)g_h2t : Ap;

    int tid = threadIdx.x;
    int bm = blockIdx.x * BM;
    int bn = blockIdx.y * BN;

    // global->smem loaders: rA in [0,64), each thread covers rows rA and rA+64 of A,
    // row rA of B-tile; kq = 4-float chunk within BK.
    int rA = tid >> 2;
    int kq = (tid & 3) * 4;
    size_t aoff0, aoff1;
    {
        int m0 = bm + rA;
        if (FC2) { aoff0 = (size_t)m0 * CA_; }
        else { int bt = m0 / HW_, sp = m0 - bt * HW_;
               aoff0 = ((size_t)(bt * L_ + 1 + sp)) * CIN_; }
        int m1 = m0 + 64;
        if (FC2) { aoff1 = (size_t)m1 * CA_; }
        else { int bt = m1 / HW_, sp = m1 - bt * HW_;
               aoff1 = ((size_t)(bt * L_ + 1 + sp)) * CIN_; }
    }
    size_t boff = (size_t)(bn + rA) * K;

    // fragment ids
    int lane = tid & 31, warp = tid >> 5;
    int g  = lane >> 2, tg = lane & 3;
    int wm = (warp & 3) * 32;      // 4 warps along M
    int wn = (warp >> 2) * 32;     // 2 warps along N

    float acc[2][4][4];
#pragma unroll
    for (int i = 0; i < 2; i++)
#pragma unroll
        for (int j = 0; j < 4; j++)
#pragma unroll
            for (int l = 0; l < 4; l++) acc[i][j][l] = 0.f;

    // prologue: stage tile 0
    {
        float4 av0 = *(const float4*)(A + aoff0 + kq);
        float4 av1 = *(const float4*)(A + aoff1 + kq);
        float4 bv  = *(const float4*)(W + boff + kq);
        float* pa0 = &As[0][rA * LDA + kq];
        float* pa1 = &As[0][(rA + 64) * LDA + kq];
        float* pb  = &Bs[0][rA * LDA + kq];
        pa0[0] = to_tf32(av0.x); pa0[1] = to_tf32(av0.y); pa0[2] = to_tf32(av0.z); pa0[3] = to_tf32(av0.w);
        pa1[0] = to_tf32(av1.x); pa1[1] = to_tf32(av1.y); pa1[2] = to_tf32(av1.z); pa1[3] = to_tf32(av1.w);
        pb [0] = to_tf32(bv.x);  pb [1] = to_tf32(bv.y);  pb [2] = to_tf32(bv.z);  pb [3] = to_tf32(bv.w);
    }
    __syncthreads();

    const int KT = K / BK;
    for (int kt = 0; kt < KT; kt++) {
        int cur = kt & 1;
        float4 av0, av1, bv;
        bool more = (kt + 1 < KT);
        if (more) {
            int ko = (kt + 1) * BK + kq;
            av0 = *(const float4*)(A + aoff0 + ko);
            av1 = *(const float4*)(A + aoff1 + ko);
            bv  = *(const float4*)(W + boff + ko);
        }
#pragma unroll
        for (int ks = 0; ks < 2; ks++) {
            int k = ks * 8;
            uint32_t af[2][4], bf[4][2];
#pragma unroll
            for (int mi = 0; mi < 2; mi++) {
                int r0 = wm + mi * 16;
                af[mi][0] = __float_as_uint(As[cur][(r0 + g)     * LDA + k + tg]);
                af[mi][1] = __float_as_uint(As[cur][(r0 + g + 8) * LDA + k + tg]);
                af[mi][2] = __float_as_uint(As[cur][(r0 + g)     * LDA + k + tg + 4]);
                af[mi][3] = __float_as_uint(As[cur][(r0 + g + 8) * LDA + k + tg + 4]);
            }
#pragma unroll
            for (int ni = 0; ni < 4; ni++) {
                int nn = wn + ni * 8 + g;
                bf[ni][0] = __float_as_uint(Bs[cur][nn * LDA + k + tg]);
                bf[ni][1] = __float_as_uint(Bs[cur][nn * LDA + k + tg + 4]);
            }
#pragma unroll
            for (int mi = 0; mi < 2; mi++)
#pragma unroll
                for (int ni = 0; ni < 4; ni++)
                    mma_tf32(acc[mi][ni], af[mi], bf[ni]);
        }
        if (more) {
            int nxt = cur ^ 1;
            float* pa0 = &As[nxt][rA * LDA + kq];
            float* pa1 = &As[nxt][(rA + 64) * LDA + kq];
            float* pb  = &Bs[nxt][rA * LDA + kq];
            pa0[0] = to_tf32(av0.x); pa0[1] = to_tf32(av0.y); pa0[2] = to_tf32(av0.z); pa0[3] = to_tf32(av0.w);
            pa1[0] = to_tf32(av1.x); pa1[1] = to_tf32(av1.y); pa1[2] = to_tf32(av1.z); pa1[3] = to_tf32(av1.w);
            pb [0] = to_tf32(bv.x);  pb [1] = to_tf32(bv.y);  pb [2] = to_tf32(bv.z);  pb [3] = to_tf32(bv.w);
        }
        __syncthreads();
    }

    // epilogue  (c0: row g col 2tg; c1: +1 col; c2: row g+8; c3: row g+8 col+1)
#pragma unroll
    for (int mi = 0; mi < 2; mi++) {
#pragma unroll
        for (int ni = 0; ni < 4; ni++) {
            int n = bn + wn + ni * 8 + tg * 2;
            float2 b2 = *(const float2*)(bias + n);
#pragma unroll
            for (int half = 0; half < 2; half++) {
                int m = bm + wm + mi * 16 + g + half * 8;
                float v0 = acc[mi][ni][half * 2 + 0] + b2.x;
                float v1 = acc[mi][ni][half * 2 + 1] + b2.y;
                if (FC2) {
                    int bt = m / HW_, sp = m - bt * HW_;
                    size_t addr = ((size_t)(bt * L_ + 1 + sp)) * CIN_ + n;
                    float2 xv = *(const float2*)(xres + addr);
                    float2 o; o.x = v0 + xv.x; o.y = v1 + xv.y;
                    *(float2*)(outp + addr) = o;
                } else {
                    float2 o; o.x = v0; o.y = v1;
                    *(float2*)(g_h1t + (size_t)m * CA_ + n) = o;
                }
            }
        }
    }
}

// per-batch 2D transpose. mode 0: g_h1t [b][ts][a] -> g_h1 [b][a][ts]
//                         mode 1: g_h2  [b][a][ts] -> g_h2t [b][ts][a]
__global__ void transpose_k(int mode)
{
    __shared__ float tile[32][33];
    const float* in;
    float* out;
    int R, C;
    if (mode == 0) { in = g_h1t; out = g_h1;  R = TS_; C = CA_; }
    else           { in = g_h2;  out = g_h2t; R = CA_; C = TS_; }
    int b = blockIdx.z;
    in  += (size_t)b * R * C;
    out += (size_t)b * R * C;
    int c0 = blockIdx.x * 32, r0 = blockIdx.y * 32;
    int tx = threadIdx.x, ty = threadIdx.y;
#pragma unroll
    for (int j = 0; j < 32; j += 8)
        tile[ty + j][tx] = in[(size_t)(r0 + ty + j) * C + c0 + tx];
    __syncthreads();
#pragma unroll
    for (int j = 0; j < 32; j += 8)
        out[(size_t)(c0 + ty + j) * R + r0 + tx] = tile[tx][ty + j];
}

// Fused depthwise conv stage: one block per (b, c) plane of [16,14,14].
// mid = (conv1+conv2+conv3)/3 + h ;  out = mid + proj(mid)
__global__ __launch_bounds__(256) void conv_fused(
    const float* __restrict__ w1, const float* __restrict__ b1,
    const float* __restrict__ w2, const float* __restrict__ b2,
    const float* __restrict__ w3, const float* __restrict__ b3,
    const float* __restrict__ pw, const float* __restrict__ pb)
{
    __shared__ float sin_[TS_];
    __shared__ float smid[TS_];
    __shared__ float sw[46];

    int blk = blockIdx.x;           // b*384 + c
    int c   = blk % CA_;
    int tid = threadIdx.x;

    if (tid < 3)        sw[tid]      = w1[c * 3 + tid];
    else if (tid < 12)  sw[tid]      = w2[c * 9 + (tid - 3)];
    else if (tid < 39)  sw[tid]      = w3[c * 27 + (tid - 12)];
    else if (tid < 42)  sw[tid]      = pw[c * 3 + (tid - 39)];
    else if (tid == 42) sw[42] = b1[c];
    else if (tid == 43) sw[43] = b2[c];
    else if (tid == 44) sw[44] = b3[c];
    else if (tid == 45) sw[45] = pb[c];

    const float* in = g_h1 + (size_t)blk * TS_;
    for (int i = tid; i < TS_; i += 256) sin_[i] = in[i];
    __syncthreads();

    for (int i = tid; i < TS_; i += 256) {
        int t  = i / HW_;
        int sp = i - t * HW_;
        int y  = sp / 14;
        int xw = sp - y * 14;
        float v = sin_[i];

        float c1 = sw[42];
#pragma unroll
        for (int dt = -1; dt <= 1; dt++) {
            int tt = t + dt;
            if (tt >= 0 && tt < T_)
                c1 += sw[dt + 1] * sin_[tt * HW_ + sp];
        }
        float c2 = sw[43];
#pragma unroll
        for (int dy = -1; dy <= 1; dy++) {
            int yy = y + dy;
            if (yy < 0 || yy >= 14) continue;
#pragma unroll
            for (int dx = -1; dx <= 1; dx++) {
                int xx = xw + dx;
                if (xx < 0 || xx >= 14) continue;
                c2 += sw[3 + (dy + 1) * 3 + (dx + 1)] * sin_[t * HW_ + yy * 14 + xx];
            }
        }
        float c3 = sw[44];
#pragma unroll
        for (int dt = -1; dt <= 1; dt++) {
            int tt = t + dt;
            if (tt < 0 || tt >= T_) continue;
#pragma unroll
            for (int dy = -1; dy <= 1; dy++) {
                int yy = y + dy;
                if (yy < 0 || yy >= 14) continue;
#pragma unroll
                for (int dx = -1; dx <= 1; dx++) {
                    int xx = xw + dx;
                    if (xx < 0 || xx >= 14) continue;
                    c3 += sw[12 + (dt + 1) * 9 + (dy + 1) * 3 + (dx + 1)]
                          * sin_[tt * HW_ + yy * 14 + xx];
                }
            }
        }
        smid[i] = (c1 + c2 + c3) * (1.0f / 3.0f) + v;
    }
    __syncthreads();

    float* outp = g_h2 + (size_t)blk * TS_;
    for (int i = tid; i < TS_; i += 256) {
        int t  = i / HW_;
        int sp = i - t * HW_;
        float o = smid[i] + sw[45];
#pragma unroll
        for (int dt = -1; dt <= 1; dt++) {
            int tt = t + dt;
            if (tt >= 0 && tt < T_)
                o += sw[39 + dt + 1] * smid[tt * HW_ + sp];
        }
        outp[i] = o;
    }
}

// Copy CLS-token rows of x to out (GEMM epilogue covers all l>=1 rows).
__global__ void cls_copy(const float* __restrict__ x, float* __restrict__ out)
{
    int i = blockIdx.x * 256 + threadIdx.x;
    if (i < BT_ * CIN_) {
        int bt = i / CIN_, cc = i - bt * CIN_;
        size_t addr = (size_t)bt * L_ * CIN_ + cc;   // l = 0 row
        out[addr] = x[addr];
    }
}

extern "C" void kernel_launch(void* const* d_in, const int* in_sizes, int n_in,
                              void* d_out, int out_size)
{
    const float* x       = (const float*)d_in[0];
    const float* fc1_w   = (const float*)d_in[1];
    const float* fc1_b   = (const float*)d_in[2];
    const float* conv1_w = (const float*)d_in[3];
    const float* conv1_b = (const float*)d_in[4];
    const float* conv2_w = (const float*)d_in[5];
    const float* conv2_b = (const float*)d_in[6];
    const float* conv3_w = (const float*)d_in[7];
    const float* conv3_b = (const float*)d_in[8];
    const float* proj_w  = (const float*)d_in[9];
    const float* proj_b  = (const float*)d_in[10];
    const float* fc2_w   = (const float*)d_in[11];
    const float* fc2_b   = (const float*)d_in[12];
    float* out = (float*)d_out;

    // fc1: [M, 768] @ [384, 768]^T -> g_h1t
    gemm_k<false><<<dim3(M_ / BM, CA_ / BN), 256>>>(x, fc1_w, fc1_b, nullptr, nullptr);
    // -> channel-plane layout
    transpose_k<<<dim3(CA_ / 32, TS_ / 32, B_), dim3(32, 8)>>>(0);
    // fused depthwise conv stage
    conv_fused<<<B_ * CA_, 256>>>(conv1_w, conv1_b, conv2_w, conv2_b,
                                  conv3_w, conv3_b, proj_w, proj_b);
    // -> token-major layout
    transpose_k<<<dim3(TS_ / 32, CA_ / 32, B_), dim3(32, 8)>>>(1);
    // fc2 + residual: [M, 384] @ [768, 384]^T + x -> out
    gemm_k<true><<<dim3(M_ / BM, CIN_ / BN), 256>>>(nullptr, fc2_w, fc2_b, x, out);
    // CLS rows
    cls_copy<<<(BT_ * CIN_ + 255) / 256, 256>>>(x, out);
}

// round 17
// speedup vs baseline: 1.3007x; 1.3007x over previous
#include <cuda_runtime.h>
#include <cstdint>

// Problem constants
#define B_    8
#define T_    16
#define HW_   196
#define TS_   3136      // T_*HW_
#define CA_   384
#define CIN_  768
#define L_    197
#define BT_   128
#define M_    25088     // BT_*196

// Scratch (device globals — no allocations allowed)
__device__ float g_h1 [M_ * CA_];   // fc1 out, conv layout [b][a][ts]
__device__ float g_h2 [M_ * CA_];   // conv out, [b][a][ts]
__device__ float g_h2t[M_ * CA_];   // token-major [tok][a]

// ---------------- helpers ----------------
__device__ __forceinline__ uint32_t smem_u32(const void* p) {
    uint32_t a;
    asm("{ .reg .u64 t; cvta.to.shared.u64 t, %1; cvt.u32.u64 %0, t; }" : "=r"(a) : "l"(p));
    return a;
}
__device__ __forceinline__ void mma_tf32(float* d, const uint32_t* a, const uint32_t* b) {
    asm volatile(
        "mma.sync.aligned.m16n8k8.row.col.f32.tf32.tf32.f32 "
        "{%0,%1,%2,%3}, {%4,%5,%6,%7}, {%8,%9}, {%0,%1,%2,%3};\n"
        : "+f"(d[0]), "+f"(d[1]), "+f"(d[2]), "+f"(d[3])
        : "r"(a[0]), "r"(a[1]), "r"(a[2]), "r"(a[3]), "r"(b[0]), "r"(b[1]));
}
#define LDSM4(r0, r1, r2, r3, addr) \
    asm volatile("ldmatrix.sync.aligned.m8n8.x4.shared.b16 {%0,%1,%2,%3}, [%4];" \
        : "=r"(r0), "=r"(r1), "=r"(r2), "=r"(r3) : "r"(addr))
#define CVT_TF32(r) asm("cvt.rna.tf32.f32 %0, %0;" : "+r"(r))
#define CP16(dst, src) \
    asm volatile("cp.async.cg.shared.global [%0], [%1], 16;" \
        :: "r"(dst), "l"(src))
#define CP_COMMIT() asm volatile("cp.async.commit_group;")
#define CP_WAIT1()  asm volatile("cp.async.wait_group 1;")

// Tile config: BM=128, BN=128, BK=16, 256 threads, 8 warps in 2(M)x4(N),
// warp tile 64x32 -> mi in [0,4), ni in [0,4). smem pitch 80B/row (LDA=20
// floats): ldmatrix row addrs r*20+c*4 hit 8 distinct bank groups.
#define BKP 20   // floats per 16-float K row (80 bytes)

// FC1: A = x tokens (skip CLS), B = fc1_w[384][768]; out -> g_h1 conv layout (+bias)
// FC2: A = g_h2t tokens,        B = fc2_w[768][384]; out -> d_out (+bias+residual)
template<int K, bool FC1>
__global__ __launch_bounds__(256)
void gemm_lg(const float* __restrict__ Ain, const float* __restrict__ Bw,
             const float* __restrict__ bias, const float* __restrict__ xres,
             float* __restrict__ outp)
{
    __shared__ float sA[2][128 * BKP];
    __shared__ float sB[2][128 * BKP];

    const int tid  = threadIdx.x;
    const int w    = tid >> 5;
    const int lane = tid & 31;
    const int bn   = blockIdx.x * 128;   // weight-channel tile
    const int bm   = blockIdx.y * 128;   // token tile

    const float* A = FC1 ? Ain : (const float*)g_h2t;

    // ---- staging: r = tile row (0..127), cpair = first 16B chunk (0 or 2) ----
    const int r     = tid >> 1;
    const int cpair = (tid & 1) * 2;
    const float* aSrc;
    if (FC1) {
        int m = bm + r; int bt = m / HW_; int sp = m - bt * HW_;
        aSrc = A + (size_t)(bt * L_ + 1 + sp) * CIN_ + cpair * 4;
    } else {
        aSrc = A + (size_t)(bm + r) * K + cpair * 4;
    }
    const float* bSrc = Bw + (size_t)(bn + r) * K + cpair * 4;
    uint32_t uA[2], uB[2];
    uA[0] = smem_u32(&sA[0][0]) + r * 80 + cpair * 16;
    uA[1] = smem_u32(&sA[1][0]) + r * 80 + cpair * 16;
    uB[0] = smem_u32(&sB[0][0]) + r * 80 + cpair * 16;
    uB[1] = smem_u32(&sB[1][0]) + r * 80 + cpair * 16;

    // ---- fragment lane geometry ----
    const int wm = (w & 1) * 64;
    const int wn = (w >> 1) * 32;
    const int q  = lane >> 3;
    const int rr = lane & 7;
    uint32_t aoff[4], boff[2];
#pragma unroll
    for (int mi = 0; mi < 4; mi++)
        aoff[mi] = (uint32_t)((wm + mi * 16 + (q & 1) * 8 + rr) * 80 + (q >> 1) * 16);
#pragma unroll
    for (int n2 = 0; n2 < 2; n2++)
        boff[n2] = (uint32_t)((wn + n2 * 16 + (q >> 1) * 8 + rr) * 80 + (q & 1) * 16);
    const uint32_t sA0 = smem_u32(&sA[0][0]), sA1 = smem_u32(&sA[1][0]);
    const uint32_t sB0 = smem_u32(&sB[0][0]), sB1 = smem_u32(&sB[1][0]);

    float acc[4][4][4];
#pragma unroll
    for (int i = 0; i < 4; i++)
#pragma unroll
        for (int j = 0; j < 4; j++)
#pragma unroll
            for (int l = 0; l < 4; l++) acc[i][j][l] = 0.f;

    const int KT = K / 16;
    // prologue: stages 0,1
#pragma unroll
    for (int s = 0; s < 2; s++) {
        const float* ap = aSrc + s * 16;
        const float* bp = bSrc + s * 16;
        CP16(uA[s],      ap);
        CP16(uA[s] + 16, ap + 4);
        CP16(uB[s],      bp);
        CP16(uB[s] + 16, bp + 4);
        CP_COMMIT();
    }

    for (int kt = 0; kt < KT; kt++) {
        const int s = kt & 1;
        CP_WAIT1();
        __syncthreads();

        const uint32_t bA = s ? sA1 : sA0;
        const uint32_t bB = s ? sB1 : sB0;
#pragma unroll
        for (int ks = 0; ks < 2; ks++) {
            uint32_t af[4][4], bf[4][2];
#pragma unroll
            for (int mi = 0; mi < 4; mi++) {
                LDSM4(af[mi][0], af[mi][1], af[mi][2], af[mi][3],
                      bA + aoff[mi] + ks * 32);
                CVT_TF32(af[mi][0]); CVT_TF32(af[mi][1]);
                CVT_TF32(af[mi][2]); CVT_TF32(af[mi][3]);
            }
#pragma unroll
            for (int n2 = 0; n2 < 2; n2++) {
                uint32_t b0, b1, b2, b3;
                LDSM4(b0, b1, b2, b3, bB + boff[n2] + ks * 32);
                CVT_TF32(b0); CVT_TF32(b1); CVT_TF32(b2); CVT_TF32(b3);
                bf[n2 * 2][0] = b0;     bf[n2 * 2][1] = b1;
                bf[n2 * 2 + 1][0] = b2; bf[n2 * 2 + 1][1] = b3;
            }
#pragma unroll
            for (int mi = 0; mi < 4; mi++)
#pragma unroll
                for (int ni = 0; ni < 4; ni++)
                    mma_tf32(acc[mi][ni], af[mi], bf[ni]);
        }
        __syncthreads();

        // prefetch kt+2 into stage s
        if (kt + 2 < KT) {
            const float* ap = aSrc + (kt + 2) * 16;
            const float* bp = bSrc + (kt + 2) * 16;
            CP16(uA[s],      ap);
            CP16(uA[s] + 16, ap + 4);
            CP16(uB[s],      bp);
            CP16(uB[s] + 16, bp + 4);
        }
        CP_COMMIT();
    }

    // ---- epilogue ----
    const int g  = lane >> 2;
    const int tg = lane & 3;
#pragma unroll
    for (int mi = 0; mi < 4; mi++) {
        int m0 = bm + wm + mi * 16 + g;          // tokens m0 and m0+8
#pragma unroll
        for (int half = 0; half < 2; half++) {
            int m  = m0 + half * 8;
            int bt = m / HW_, sp = m - bt * HW_;
#pragma unroll
            for (int ni = 0; ni < 4; ni++) {
                int n = bn + wn + ni * 8 + tg * 2;
                float2 bb = *(const float2*)(bias + n);
                float v0 = acc[mi][ni][half * 2 + 0] + bb.x;
                float v1 = acc[mi][ni][half * 2 + 1] + bb.y;
                if (FC1) {
                    // g_h1[b][ch][t*196+sp]
                    int b = bt >> 4, t = bt & 15;
                    size_t base = (size_t)b * (CA_ * TS_) + (size_t)(t * HW_ + sp);
                    g_h1[base + (size_t)n * TS_]       = v0;
                    g_h1[base + (size_t)(n + 1) * TS_] = v1;
                } else {
                    size_t addr = (size_t)(bt * L_ + 1 + sp) * CIN_ + n;
                    float2 xv = *(const float2*)(xres + addr);
                    float2 o; o.x = v0 + xv.x; o.y = v1 + xv.y;
                    *(float2*)(outp + addr) = o;
                }
            }
        }
    }
}

// ---------------- transpose: g_h2 [b][a][ts] -> g_h2t [b][ts][a] ----------------
__global__ void transpose_k()
{
    __shared__ float tile[32][33];
    const int R = CA_, C = TS_;
    int b = blockIdx.z;
    const float* in = g_h2 + (size_t)b * R * C;
    float* out      = g_h2t + (size_t)b * R * C;
    int c0 = blockIdx.x * 32, r0 = blockIdx.y * 32;
    int tx = threadIdx.x, ty = threadIdx.y;
#pragma unroll
    for (int j = 0; j < 32; j += 8)
        tile[ty + j][tx] = in[(size_t)(r0 + ty + j) * C + c0 + tx];
    __syncthreads();
#pragma unroll
    for (int j = 0; j < 32; j += 8)
        out[(size_t)(c0 + ty + j) * R + r0 + tx] = tile[tx][ty + j];
}

// ---------------- fused depthwise conv stage ----------------
__global__ __launch_bounds__(256) void conv_fused(
    const float* __restrict__ w1, const float* __restrict__ b1,
    const float* __restrict__ w2, const float* __restrict__ b2,
    const float* __restrict__ w3, const float* __restrict__ b3,
    const float* __restrict__ pw, const float* __restrict__ pb)
{
    __shared__ float sin_[TS_];
    __shared__ float smid[TS_];
    __shared__ float sw[46];

    int blk = blockIdx.x;           // b*384 + c
    int c   = blk % CA_;
    int tid = threadIdx.x;

    if (tid < 3)        sw[tid] = w1[c * 3 + tid];
    else if (tid < 12)  sw[tid] = w2[c * 9 + (tid - 3)];
    else if (tid < 39)  sw[tid] = w3[c * 27 + (tid - 12)];
    else if (tid < 42)  sw[tid] = pw[c * 3 + (tid - 39)];
    else if (tid == 42) sw[42] = b1[c];
    else if (tid == 43) sw[43] = b2[c];
    else if (tid == 44) sw[44] = b3[c];
    else if (tid == 45) sw[45] = pb[c];

    const float* in = g_h1 + (size_t)blk * TS_;
    for (int i = tid; i < TS_; i += 256) sin_[i] = in[i];
    __syncthreads();

    for (int i = tid; i < TS_; i += 256) {
        int t  = i / HW_;
        int sp = i - t * HW_;
        int y  = sp / 14;
        int xw = sp - y * 14;
        float v = sin_[i];

        float c1 = sw[42];
#pragma unroll
        for (int dt = -1; dt <= 1; dt++) {
            int tt = t + dt;
            if (tt >= 0 && tt < T_)
                c1 += sw[dt + 1] * sin_[tt * HW_ + sp];
        }
        float c2 = sw[43];
#pragma unroll
        for (int dy = -1; dy <= 1; dy++) {
            int yy = y + dy;
            if (yy < 0 || yy >= 14) continue;
#pragma unroll
            for (int dx = -1; dx <= 1; dx++) {
                int xx = xw + dx;
                if (xx < 0 || xx >= 14) continue;
                c2 += sw[3 + (dy + 1) * 3 + (dx + 1)] * sin_[t * HW_ + yy * 14 + xx];
            }
        }
        float c3 = sw[44];
#pragma unroll
        for (int dt = -1; dt <= 1; dt++) {
            int tt = t + dt;
            if (tt < 0 || tt >= T_) continue;
#pragma unroll
            for (int dy = -1; dy <= 1; dy++) {
                int yy = y + dy;
                if (yy < 0 || yy >= 14) continue;
#pragma unroll
                for (int dx = -1; dx <= 1; dx++) {
                    int xx = xw + dx;
                    if (xx < 0 || xx >= 14) continue;
                    c3 += sw[12 + (dt + 1) * 9 + (dy + 1) * 3 + (dx + 1)]
                          * sin_[tt * HW_ + yy * 14 + xx];
                }
            }
        }
        smid[i] = (c1 + c2 + c3) * (1.0f / 3.0f) + v;
    }
    __syncthreads();

    float* outp = g_h2 + (size_t)blk * TS_;
    for (int i = tid; i < TS_; i += 256) {
        int t  = i / HW_;
        int sp = i - t * HW_;
        float o = smid[i] + sw[45];
#pragma unroll
        for (int dt = -1; dt <= 1; dt++) {
            int tt = t + dt;
            if (tt >= 0 && tt < T_)
                o += sw[39 + dt + 1] * smid[tt * HW_ + sp];
        }
        outp[i] = o;
    }
}

// Copy CLS-token rows of x to out.
__global__ void cls_copy(const float* __restrict__ x, float* __restrict__ out)
{
    int i = blockIdx.x * 256 + threadIdx.x;
    if (i < BT_ * CIN_) {
        int bt = i / CIN_, cc = i - bt * CIN_;
        size_t addr = (size_t)bt * L_ * CIN_ + cc;   // l = 0 row
        out[addr] = x[addr];
    }
}

extern "C" void kernel_launch(void* const* d_in, const int* in_sizes, int n_in,
                              void* d_out, int out_size)
{
    const float* x       = (const float*)d_in[0];
    const float* fc1_w   = (const float*)d_in[1];
    const float* fc1_b   = (const float*)d_in[2];
    const float* conv1_w = (const float*)d_in[3];
    const float* conv1_b = (const float*)d_in[4];
    const float* conv2_w = (const float*)d_in[5];
    const float* conv2_b = (const float*)d_in[6];
    const float* conv3_w = (const float*)d_in[7];
    const float* conv3_b = (const float*)d_in[8];
    const float* proj_w  = (const float*)d_in[9];
    const float* proj_b  = (const float*)d_in[10];
    const float* fc2_w   = (const float*)d_in[11];
    const float* fc2_b   = (const float*)d_in[12];
    float* out = (float*)d_out;

    // fc1 (ldmatrix + cp.async): tokens x fc1_w^T -> g_h1 (conv layout, fused transpose)
    gemm_lg<CIN_, true><<<dim3(CA_ / 128, M_ / 128), 256>>>(
        x, fc1_w, fc1_b, nullptr, nullptr);
    // fused depthwise conv stage
    conv_fused<<<B_ * CA_, 256>>>(conv1_w, conv1_b, conv2_w, conv2_b,
                                  conv3_w, conv3_b, proj_w, proj_b);
    // -> token-major layout for fc2 A operand
    transpose_k<<<dim3(TS_ / 32, CA_ / 32, B_), dim3(32, 8)>>>();
    // fc2: tokens x fc2_w^T + bias + residual -> out
    gemm_lg<CA_, false><<<dim3(CIN_ / 128, M_ / 128), 256>>>(
        nullptr, fc2_w, fc2_b, x, out);
    // CLS rows
    cls_copy<<<(BT_ * CIN_ + 255) / 256, 256>>>(x, out);
}